// round 5
// baseline (speedup 1.0000x reference)
#include <cuda_runtime.h>
#include <cstdint>
#include <cstddef>

#define N_NODES 32768
#define N_EDGES 524288
typedef unsigned long long u64t;

// ---- scratch (device globals; allocations forbidden) ----
__device__ float g_x[(size_t)N_NODES * 256];   // [0:64]=x0, [64+u*3+i]=x1[u][i]
__device__ float g_m[(size_t)N_NODES * 512];   // [0:128]=m0, [128+v*3+i]=m1[v][i]
__device__ float g_wt0[64 * 640];              // W_skip0 as [v][w][u]
__device__ float g_wt1[64 * 640];

#define C_UP      0.125f
#define C_R1      0.35355339059327373f
#define C_R       0.125f
#define C_LIN     0.00552427172801990f
#define C_SKIP    0.03952847075210474f
#define INV_SQRT3 0.5773502691896258f

__device__ __forceinline__ float silu_f(float x) {
    return __fdividef(x, 1.0f + __expf(-x));
}
__device__ __forceinline__ void red_add_v4(float* a, float x, float y, float z, float w) {
    asm volatile("red.global.add.v4.f32 [%0], {%1,%2,%3,%4};"
                 :: "l"(a), "f"(x), "f"(y), "f"(z), "f"(w) : "memory");
}
// ---- packed f32x2 helpers (Blackwell) ----
__device__ __forceinline__ u64t pk2(float x) {
    u64t r; asm("mov.b64 %0, {%1, %1};" : "=l"(r) : "f"(x)); return r;
}
__device__ __forceinline__ void fma2(u64t& d, u64t a, u64t b) {
    asm("fma.rn.f32x2 %0, %1, %2, %0;" : "+l"(d) : "l"(a), "l"(b));
}
__device__ __forceinline__ float2 up2(u64t v) {
    float2 f; asm("mov.b64 {%0, %1}, %2;" : "=f"(f.x), "=f"(f.y) : "l"(v)); return f;
}

// ==== K_prep: W_skip (64,64,10)[u,v,w] -> [v][w][u] ====
__global__ void k_prep(const float* __restrict__ Ws0, const float* __restrict__ Ws1) {
    int idx = blockIdx.x * 256 + threadIdx.x;   // 0..40959
    int v = idx / 640, r = idx % 640;
    int w = r / 64, u = r % 64;
    g_wt0[idx] = Ws0[u * 640 + v * 10 + w];
    g_wt1[idx] = Ws1[u * 640 + v * 10 + w];
}

// ==== K0: node up-projection (8 nodes/block) ====
__global__ __launch_bounds__(256) void k_node_up(const float* __restrict__ nf,
                                                 const float* __restrict__ Wu0,
                                                 const float* __restrict__ Wu1) {
    __shared__ float sW0[4096], sW1[4096], sIn[2048];
    const int t = threadIdx.x;
    for (int i = t; i < 4096; i += 256) { sW0[i] = Wu0[i]; sW1[i] = Wu1[i]; }
    const int n0 = blockIdx.x * 8;
    for (int i = t; i < 2048; i += 256) sIn[i] = nf[(size_t)n0 * 256 + i];
    __syncthreads();
    const int j = t >> 6, u = t & 63;
    const int off0 = (j == 0) ? 0 : (63 + j);
    const int st = (j == 0) ? 1 : 3;
    const float* W = (j == 0) ? sW0 : sW1;
    const int oo = (j == 0) ? u : (64 + u * 3 + (j - 1));
    for (int c = 0; c < 2; c++) {
        float acc[4] = {0.f, 0.f, 0.f, 0.f};
        #pragma unroll 8
        for (int v = 0; v < 64; v++) {
            float w = W[v * 64 + u];
            #pragma unroll
            for (int r = 0; r < 4; r++)
                acc[r] += sIn[(c * 4 + r) * 256 + off0 + v * st] * w;
        }
        #pragma unroll
        for (int r = 0; r < 4; r++)
            g_x[(size_t)(n0 + c * 4 + r) * 256 + oo] = acc[r] * C_UP;
    }
}

// ==== K1: persistent edge kernel, 512 threads, 128 edges/tile, f32x2 ====
#define ST_H 68
#define OFF_WR1 0
#define OFF_WR2 512
#define OFF_WR3 4608
#define OFF_WR4 8704
#define OFF_HA  25088
#define OFF_HB  (OFF_HA + 128*ST_H)       // 33792
#define OFF_EF  (OFF_HB + 128*ST_H)       // 42496
#define OFF_EA  (OFF_EF + 1024)           // 43520
#define OFF_SRC (OFF_EA + 512)            // 44032
#define OFF_DST (OFF_SRC + 128)           // 44160
#define K1_SMEM_FLOATS (OFF_DST + 128)    // 44288 -> 177152 B

template<int K, bool SILU>
__device__ __forceinline__ void gemm2(const float* __restrict__ A, int astride,
                                      const float* __restrict__ B,
                                      float* __restrict__ O,
                                      float scale, int e0l, int e1l, int cb) {
    u64t acc[2][4];
    #pragma unroll
    for (int r = 0; r < 2; r++)
        #pragma unroll
        for (int j = 0; j < 4; j++) acc[r][j] = 0ull;
    #pragma unroll 8
    for (int k = 0; k < K; k++) {
        u64t pa0 = pk2(A[e0l * astride + k]);
        u64t pa1 = pk2(A[e1l * astride + k]);
        const ulonglong2* Bp = (const ulonglong2*)(B + k * 64 + cb);
        ulonglong2 bl = Bp[0], bh = Bp[1];
        fma2(acc[0][0], pa0, bl.x); fma2(acc[0][1], pa0, bl.y);
        fma2(acc[0][2], pa0, bh.x); fma2(acc[0][3], pa0, bh.y);
        fma2(acc[1][0], pa1, bl.x); fma2(acc[1][1], pa1, bl.y);
        fma2(acc[1][2], pa1, bh.x); fma2(acc[1][3], pa1, bh.y);
    }
    #pragma unroll
    for (int r = 0; r < 2; r++) {
        const int e = r ? e1l : e0l;
        float v[8];
        #pragma unroll
        for (int j = 0; j < 4; j++) {
            float2 f = up2(acc[r][j]);
            float x0 = f.x * scale, x1 = f.y * scale;
            v[j*2]   = SILU ? silu_f(x0) : x0;
            v[j*2+1] = SILU ? silu_f(x1) : x1;
        }
        float* op = O + e * ST_H + cb;
        *(float4*)(op)     = make_float4(v[0], v[1], v[2], v[3]);
        *(float4*)(op + 4) = make_float4(v[4], v[5], v[6], v[7]);
    }
}

// layer-4: one edge, one 64-col chunk cc, B=sWr4 (stride 256), out 8 floats
__device__ __forceinline__ void l4_1e(const float* __restrict__ sHa,
                                      const float* __restrict__ sWr4,
                                      int el, int cb, int cc, float (&o)[8]) {
    u64t acc[4] = {0ull, 0ull, 0ull, 0ull};
    const float* B = sWr4 + cc * 64 + cb;
    #pragma unroll 8
    for (int k = 0; k < 64; k++) {
        u64t pa = pk2(sHa[el * ST_H + k]);
        const ulonglong2* Bp = (const ulonglong2*)(B + k * 256);
        ulonglong2 bl = Bp[0], bh = Bp[1];
        fma2(acc[0], pa, bl.x); fma2(acc[1], pa, bl.y);
        fma2(acc[2], pa, bh.x); fma2(acc[3], pa, bh.y);
    }
    #pragma unroll
    for (int j = 0; j < 4; j++) {
        float2 f = up2(acc[j]);
        o[j*2]   = f.x * C_R;
        o[j*2+1] = f.y * C_R;
    }
}

__global__ __launch_bounds__(512, 1) void k_edge(const float* __restrict__ ef,
                                                 const float* __restrict__ ea,
                                                 const int* __restrict__ src,
                                                 const int* __restrict__ dst,
                                                 const float* __restrict__ Wr1,
                                                 const float* __restrict__ Wr2,
                                                 const float* __restrict__ Wr3,
                                                 const float* __restrict__ Wr4) {
    extern __shared__ float sm[];
    float* sWr1 = sm + OFF_WR1;
    float* sWr2 = sm + OFF_WR2;
    float* sWr3 = sm + OFF_WR3;
    float* sWr4 = sm + OFF_WR4;
    float* sHa  = sm + OFF_HA;
    float* sHb  = sm + OFF_HB;
    float* sEF  = sm + OFF_EF;
    float* sEA  = sm + OFF_EA;
    int*   sSrc = (int*)(sm + OFF_SRC);
    int*   sDst = (int*)(sm + OFF_DST);
    const int t = threadIdx.x;
    if (t < 512) sWr1[t] = Wr1[t];
    for (int i = t; i < 4096;  i += 512) { sWr2[i] = Wr2[i]; sWr3[i] = Wr3[i]; }
    for (int i = t; i < 16384; i += 512) sWr4[i] = Wr4[i];
    const int te = t >> 3, tc = t & 7;
    const int e0l = 2 * te, e1l = 2 * te + 1, cb = tc * 8;

    for (int tile = blockIdx.x; tile < N_EDGES / 128; tile += gridDim.x) {
        const int eg = tile * 128;
        __syncthreads();
        for (int i = t; i < 1024; i += 512) sEF[i] = ef[(size_t)eg * 8 + i];
        sEA[t] = ea[(size_t)eg * 4 + t];
        if (t < 128)      sSrc[t] = src[eg + t];
        else if (t < 256) sDst[t - 128] = dst[eg + t - 128];
        __syncthreads();
        gemm2<8,  true>(sEF, 8,    sWr1, sHa, C_R1, e0l, e1l, cb);
        __syncthreads();
        gemm2<64, true>(sHa, ST_H, sWr2, sHb, C_R,  e0l, e1l, cb);
        __syncthreads();
        gemm2<64, true>(sHb, ST_H, sWr3, sHa, C_R,  e0l, e1l, cb);
        __syncthreads();

        // ---- fused layer-4 + messages, one edge at a time ----
        #pragma unroll
        for (int e = 0; e < 2; e++) {
            const int el = e0l + e;
            const int sn = sSrc[el], dn = sDst[el];
            const float sh0 = sEA[el*4+0];
            const float a1 = sEA[el*4+1], a2 = sEA[el*4+2], a3 = sEA[el*4+3];
            const float* xr = g_x + (size_t)sn * 256;
            float*       mr = g_m + (size_t)dn * 512;

            float s8[8];
            {
                float4 p = *(const float4*)(xr + cb);
                float4 q = *(const float4*)(xr + cb + 4);
                s8[0]=p.x; s8[1]=p.y; s8[2]=p.z; s8[3]=p.w;
                s8[4]=q.x; s8[5]=q.y; s8[6]=q.z; s8[7]=q.w;
            }
            float acc8[8];
            // cc=0: p0 -> m0[0:64]
            l4_1e(sHa, sWr4, el, cb, 0, acc8);
            red_add_v4(mr + cb,
                       acc8[0]*s8[0]*sh0, acc8[1]*s8[1]*sh0,
                       acc8[2]*s8[2]*sh0, acc8[3]*s8[3]*sh0);
            red_add_v4(mr + cb + 4,
                       acc8[4]*s8[4]*sh0, acc8[5]*s8[5]*sh0,
                       acc8[6]*s8[6]*sh0, acc8[7]*s8[7]*sh0);
            // cc=1: p1 -> mr[128 + u*3 + i]
            l4_1e(sHa, sWr4, el, cb, 1, acc8);
            {
                float p[24];
                #pragma unroll
                for (int j = 0; j < 8; j++) {
                    float ts = acc8[j] * s8[j];
                    p[j*3+0] = ts * a1; p[j*3+1] = ts * a2; p[j*3+2] = ts * a3;
                }
                float* b = mr + 128 + cb * 3;
                #pragma unroll
                for (int r = 0; r < 6; r++)
                    red_add_v4(b + r*4, p[r*4], p[r*4+1], p[r*4+2], p[r*4+3]);
            }
            // gather v (x1)
            float vv[24];
            #pragma unroll
            for (int i = 0; i < 6; i++) {
                float4 p = *(const float4*)(xr + 64 + cb*3 + i*4);
                vv[i*4+0]=p.x; vv[i*4+1]=p.y; vv[i*4+2]=p.z; vv[i*4+3]=p.w;
            }
            // cc=2: p2 -> mr[320 + u*3 + i]
            l4_1e(sHa, sWr4, el, cb, 2, acc8);
            {
                float p[24];
                #pragma unroll
                for (int j = 0; j < 8; j++) {
                    float tv = acc8[j] * sh0;
                    p[j*3+0] = tv*vv[j*3+0]; p[j*3+1] = tv*vv[j*3+1]; p[j*3+2] = tv*vv[j*3+2];
                }
                float* b = mr + 320 + cb * 3;
                #pragma unroll
                for (int r = 0; r < 6; r++)
                    red_add_v4(b + r*4, p[r*4], p[r*4+1], p[r*4+2], p[r*4+3]);
            }
            // cc=3: p3 -> m0[64:128]
            l4_1e(sHa, sWr4, el, cb, 3, acc8);
            {
                float p[8];
                #pragma unroll
                for (int j = 0; j < 8; j++) {
                    float dv = vv[j*3+0]*a1 + vv[j*3+1]*a2 + vv[j*3+2]*a3;
                    p[j] = acc8[j] * dv * INV_SQRT3;
                }
                red_add_v4(mr + 64 + cb,     p[0], p[1], p[2], p[3]);
                red_add_v4(mr + 64 + cb + 4, p[4], p[5], p[6], p[7]);
            }
        }
    }
}

// ==== K2: node output, 8 nodes/block, 2 blocks/SM ====
#define NOB 8
#define O2_WL0 0
#define O2_WL1 8192
#define O2_M   16384
#define O2_Y   (O2_M + NOB*512)           // 20480
#define O2_A   (O2_Y + NOB*256)           // 22528
#define K2_SMEM_FLOATS (O2_A + NOB*12)    // 22624 -> 90496 B

__global__ __launch_bounds__(256, 2) void k_node_out(const float* __restrict__ na,
                                                     const float* __restrict__ Wl0,
                                                     const float* __restrict__ Wl1,
                                                     float* __restrict__ out) {
    extern __shared__ float sm[];
    float* sWl0 = sm + O2_WL0;
    float* sWl1 = sm + O2_WL1;
    float* sWt  = sm;                 // phase-B reuse of the 16384-float weight area
    float* sM   = sm + O2_M;
    float* sY   = sm + O2_Y;
    float* sA   = sm + O2_A;
    const int t = threadIdx.x;
    const int n0 = blockIdx.x * NOB;
    for (int i = t; i < 8192; i += 256) { sWl0[i] = Wl0[i]; sWl1[i] = Wl1[i]; }
    for (int i = t; i < NOB * 512; i += 256) sM[i] = g_m[(size_t)n0 * 512 + i];
    for (int i = t; i < NOB * 12; i += 256) {
        int n = i / 12, w = i % 12;
        sA[i] = (w < 10) ? na[(size_t)(n0 + n) * 10 + w] : 0.f;
    }
    __syncthreads();
    const int n4 = t >> 6, u = t & 63;

    // ---- phase A: y = m @ W_lin ----
    float y[8];
    #pragma unroll
    for (int i = 0; i < 8; i++) y[i] = 0.f;
    #pragma unroll 4
    for (int v = 0; v < 128; v++) {
        float w0 = sWl0[v * 64 + u], w1 = sWl1[v * 64 + u];
        #pragma unroll
        for (int ns = 0; ns < 2; ns++) {
            const float* m = sM + (ns * 4 + n4) * 512;
            y[ns*4+0] += m[v] * w0;
            y[ns*4+1] += m[128 + v*3 + 0] * w1;
            y[ns*4+2] += m[128 + v*3 + 1] * w1;
            y[ns*4+3] += m[128 + v*3 + 2] * w1;
        }
    }
    #pragma unroll
    for (int ns = 0; ns < 2; ns++) {
        float* yb = sY + (ns * 4 + n4) * 256;
        yb[u]       = y[ns*4+0] * C_LIN;
        yb[64 + u]  = y[ns*4+1] * C_LIN;
        yb[128 + u] = y[ns*4+2] * C_LIN;
        yb[192 + u] = y[ns*4+3] * C_LIN;
    }
    float areg[20];
    #pragma unroll
    for (int ns = 0; ns < 2; ns++)
        #pragma unroll
        for (int w = 0; w < 10; w++)
            areg[ns*10 + w] = sA[(ns*4 + n4) * 12 + w];

    // ---- phase B: z = y . (a . W_skip), W_skip [v][w][u] streamed via smem ----
    float z[8];
    #pragma unroll
    for (int i = 0; i < 8; i++) z[i] = 0.f;
    for (int vc = 0; vc < 8; vc++) {
        __syncthreads();
        const int v0 = vc * 8;
        const float4* g0p = (const float4*)(g_wt0 + (size_t)v0 * 640);
        const float4* g1p = (const float4*)(g_wt1 + (size_t)v0 * 640);
        float4* d0 = (float4*)sWt;
        float4* d1 = (float4*)(sWt + 5120);
        for (int i = t; i < 1280; i += 256) { d0[i] = g0p[i]; d1[i] = g1p[i]; }
        __syncthreads();
        #pragma unroll
        for (int v = 0; v < 8; v++) {
            const float* w0b = sWt + v * 640 + u;
            const float* w1b = sWt + 5120 + v * 640 + u;
            float g0[2] = {0.f, 0.f}, g1[2] = {0.f, 0.f};
            #pragma unroll
            for (int w = 0; w < 10; w++) {
                float lw0 = w0b[w * 64];
                float lw1 = w1b[w * 64];
                g0[0] += areg[w]      * lw0;
                g0[1] += areg[10 + w] * lw0;
                g1[0] += areg[w]      * lw1;
                g1[1] += areg[10 + w] * lw1;
            }
            #pragma unroll
            for (int ns = 0; ns < 2; ns++) {
                const float* yp = sY + (ns * 4 + n4) * 256 + v0 + v;
                z[ns*4+0] += yp[0]   * g0[ns];
                z[ns*4+1] += yp[64]  * g1[ns];
                z[ns*4+2] += yp[128] * g1[ns];
                z[ns*4+3] += yp[192] * g1[ns];
            }
        }
    }
    #pragma unroll
    for (int ns = 0; ns < 2; ns++) {
        float* o = out + (size_t)(n0 + ns * 4 + n4) * 256;
        o[u]            = z[ns*4+0] * C_SKIP;
        o[64 + u*3 + 0] = z[ns*4+1] * C_SKIP;
        o[64 + u*3 + 1] = z[ns*4+2] * C_SKIP;
        o[64 + u*3 + 2] = z[ns*4+3] * C_SKIP;
    }
}

extern "C" void kernel_launch(void* const* d_in, const int* in_sizes, int n_in,
                              void* d_out, int out_size) {
    const float* nf  = (const float*)d_in[0];
    const float* na  = (const float*)d_in[1];
    const float* ef  = (const float*)d_in[2];
    const float* ea  = (const float*)d_in[3];
    const int*   src = (const int*)d_in[4];
    const int*   dst = (const int*)d_in[5];
    const float* Wu0 = (const float*)d_in[6];
    const float* Wu1 = (const float*)d_in[7];
    const float* Wr1 = (const float*)d_in[8];
    const float* Wr2 = (const float*)d_in[9];
    const float* Wr3 = (const float*)d_in[10];
    const float* Wr4 = (const float*)d_in[11];
    const float* Wl0 = (const float*)d_in[12];
    const float* Wl1 = (const float*)d_in[13];
    const float* Ws0 = (const float*)d_in[14];
    const float* Ws1 = (const float*)d_in[15];
    float* out = (float*)d_out;

    cudaFuncSetAttribute(k_edge, cudaFuncAttributeMaxDynamicSharedMemorySize,
                         K1_SMEM_FLOATS * 4);
    cudaFuncSetAttribute(k_node_out, cudaFuncAttributeMaxDynamicSharedMemorySize,
                         K2_SMEM_FLOATS * 4);

    void* gm_ptr = nullptr;
    cudaGetSymbolAddress(&gm_ptr, g_m);
    cudaMemsetAsync(gm_ptr, 0, sizeof(float) * (size_t)N_NODES * 512, 0);

    k_prep<<<160, 256>>>(Ws0, Ws1);
    k_node_up<<<N_NODES / 8, 256>>>(nf, Wu0, Wu1);
    k_edge<<<148, 512, K1_SMEM_FLOATS * 4>>>(ef, ea, src, dst, Wr1, Wr2, Wr3, Wr4);
    k_node_out<<<N_NODES / NOB, 256, K2_SMEM_FLOATS * 4>>>(na, Wl0, Wl1, out);
}

// round 7
// speedup vs baseline: 1.3716x; 1.3716x over previous
#include <cuda_runtime.h>
#include <cstdint>
#include <cstddef>

#define N_NODES 32768
#define N_EDGES 524288

// ---- scratch (device globals; allocations forbidden) ----
__device__ float g_x[(size_t)N_NODES * 256];   // [0:64]=x0, [64+u*3+i]=x1[u][i]
__device__ float g_m[(size_t)N_NODES * 512];   // [0:128]=m0, [128+v*3+i]=m1[v][i]
__device__ float g_wt0[64 * 640];              // W_skip0 as [v][w][u]
__device__ float g_wt1[64 * 640];

#define C_UP      0.125f
#define C_R1      0.35355339059327373f
#define C_R       0.125f
#define C_LIN     0.00552427172801990f
#define C_SKIP    0.03952847075210474f
#define INV_SQRT3 0.5773502691896258f

__device__ __forceinline__ float silu_f(float x) {
    return __fdividef(x, 1.0f + __expf(-x));
}
__device__ __forceinline__ void red_add_v4(float* a, float x, float y, float z, float w) {
    asm volatile("red.global.add.v4.f32 [%0], {%1,%2,%3,%4};"
                 :: "l"(a), "f"(x), "f"(y), "f"(z), "f"(w) : "memory");
}

// ==== K_prep: W_skip (64,64,10)[u,v,w] -> [v][w][u] ====
__global__ void k_prep(const float* __restrict__ Ws0, const float* __restrict__ Ws1) {
    int idx = blockIdx.x * 256 + threadIdx.x;   // 0..40959
    int v = idx / 640, r = idx % 640;
    int w = r / 64, u = r % 64;
    g_wt0[idx] = Ws0[u * 640 + v * 10 + w];
    g_wt1[idx] = Ws1[u * 640 + v * 10 + w];
}

// ==== K0: node up-projection (8 nodes/block) ====
__global__ __launch_bounds__(256) void k_node_up(const float* __restrict__ nf,
                                                 const float* __restrict__ Wu0,
                                                 const float* __restrict__ Wu1) {
    __shared__ float sW0[4096], sW1[4096], sIn[2048];
    const int t = threadIdx.x;
    for (int i = t; i < 4096; i += 256) { sW0[i] = Wu0[i]; sW1[i] = Wu1[i]; }
    const int n0 = blockIdx.x * 8;
    for (int i = t; i < 2048; i += 256) sIn[i] = nf[(size_t)n0 * 256 + i];
    __syncthreads();
    const int j = t >> 6, u = t & 63;
    const int off0 = (j == 0) ? 0 : (63 + j);
    const int st = (j == 0) ? 1 : 3;
    const float* W = (j == 0) ? sW0 : sW1;
    const int oo = (j == 0) ? u : (64 + u * 3 + (j - 1));
    for (int c = 0; c < 2; c++) {
        float acc[4] = {0.f, 0.f, 0.f, 0.f};
        #pragma unroll 8
        for (int v = 0; v < 64; v++) {
            float w = W[v * 64 + u];
            #pragma unroll
            for (int r = 0; r < 4; r++)
                acc[r] += sIn[(c * 4 + r) * 256 + off0 + v * st] * w;
        }
        #pragma unroll
        for (int r = 0; r < 4; r++)
            g_x[(size_t)(n0 + c * 4 + r) * 256 + oo] = acc[r] * C_UP;
    }
}

// ==== K1: persistent edge kernel, 64 edges/tile, fused layer4+message ====
#define ST_H 68
#define OFF_WR1 0
#define OFF_WR2 512
#define OFF_WR3 4608
#define OFF_HA  8704
#define OFF_HB  (OFF_HA + 64*ST_H)
#define OFF_EF  (OFF_HB + 64*ST_H)
#define OFF_EA  (OFF_EF + 512)
#define OFF_SRC (OFF_EA + 256)
#define OFF_DST (OFF_SRC + 64)
#define K1_SMEM_FLOATS (OFF_DST + 64)

template<int K, bool SILU>
__device__ __forceinline__ void gemm_tile(const float* __restrict__ A, int astride,
                                          const float* __restrict__ B,
                                          float* __restrict__ O,
                                          float scale, int e0l, int e1l, int cb) {
    float acc[2][8];
    #pragma unroll
    for (int r = 0; r < 2; r++)
        #pragma unroll
        for (int j = 0; j < 8; j++) acc[r][j] = 0.f;
    #pragma unroll 8
    for (int k = 0; k < K; k++) {
        float a0 = A[e0l * astride + k];
        float a1 = A[e1l * astride + k];
        const float4 b0 = *(const float4*)(B + k * 64 + cb);
        const float4 b1 = *(const float4*)(B + k * 64 + cb + 4);
        acc[0][0] += a0*b0.x; acc[0][1] += a0*b0.y; acc[0][2] += a0*b0.z; acc[0][3] += a0*b0.w;
        acc[0][4] += a0*b1.x; acc[0][5] += a0*b1.y; acc[0][6] += a0*b1.z; acc[0][7] += a0*b1.w;
        acc[1][0] += a1*b0.x; acc[1][1] += a1*b0.y; acc[1][2] += a1*b0.z; acc[1][3] += a1*b0.w;
        acc[1][4] += a1*b1.x; acc[1][5] += a1*b1.y; acc[1][6] += a1*b1.z; acc[1][7] += a1*b1.w;
    }
    #pragma unroll
    for (int r = 0; r < 2; r++) {
        const int e = r ? e1l : e0l;
        float v[8];
        #pragma unroll
        for (int j = 0; j < 8; j++) {
            float x = acc[r][j] * scale;
            v[j] = SILU ? silu_f(x) : x;
        }
        float* op = O + e * ST_H + cb;
        *(float4*)(op)     = make_float4(v[0], v[1], v[2], v[3]);
        *(float4*)(op + 4) = make_float4(v[4], v[5], v[6], v[7]);
    }
}

__device__ __forceinline__ void l4_acc(const float* __restrict__ sHa,
                                       const float* __restrict__ Wr4,
                                       int e0l, int e1l, int cb, int cc,
                                       float (&acc)[2][8]) {
    #pragma unroll
    for (int r = 0; r < 2; r++)
        #pragma unroll
        for (int j = 0; j < 8; j++) acc[r][j] = 0.f;
    const float* B = Wr4 + cc * 64 + cb;
    #pragma unroll 8
    for (int k = 0; k < 64; k++) {
        float a0 = sHa[e0l * ST_H + k];
        float a1 = sHa[e1l * ST_H + k];
        const float4 b0 = __ldg((const float4*)(B + (size_t)k * 256));
        const float4 b1 = __ldg((const float4*)(B + (size_t)k * 256 + 4));
        acc[0][0] += a0*b0.x; acc[0][1] += a0*b0.y; acc[0][2] += a0*b0.z; acc[0][3] += a0*b0.w;
        acc[0][4] += a0*b1.x; acc[0][5] += a0*b1.y; acc[0][6] += a0*b1.z; acc[0][7] += a0*b1.w;
        acc[1][0] += a1*b0.x; acc[1][1] += a1*b0.y; acc[1][2] += a1*b0.z; acc[1][3] += a1*b0.w;
        acc[1][4] += a1*b1.x; acc[1][5] += a1*b1.y; acc[1][6] += a1*b1.z; acc[1][7] += a1*b1.w;
    }
    #pragma unroll
    for (int r = 0; r < 2; r++)
        #pragma unroll
        for (int j = 0; j < 8; j++) acc[r][j] *= C_R;
}

__global__ __launch_bounds__(256, 2) void k_edge(const float* __restrict__ ef,
                                                 const float* __restrict__ ea,
                                                 const int* __restrict__ src,
                                                 const int* __restrict__ dst,
                                                 const float* __restrict__ Wr1,
                                                 const float* __restrict__ Wr2,
                                                 const float* __restrict__ Wr3,
                                                 const float* __restrict__ Wr4) {
    extern __shared__ float sm[];
    float* sWr1 = sm + OFF_WR1;
    float* sWr2 = sm + OFF_WR2;
    float* sWr3 = sm + OFF_WR3;
    float* sHa  = sm + OFF_HA;
    float* sHb  = sm + OFF_HB;
    float* sEF  = sm + OFF_EF;
    float* sEA  = sm + OFF_EA;
    int*   sSrc = (int*)(sm + OFF_SRC);
    int*   sDst = (int*)(sm + OFF_DST);
    const int t = threadIdx.x;
    for (int i = t; i < 512;  i += 256) sWr1[i] = Wr1[i];
    for (int i = t; i < 4096; i += 256) { sWr2[i] = Wr2[i]; sWr3[i] = Wr3[i]; }
    const int te = t >> 3, tc = t & 7;
    const int e0l = 2 * te, e1l = 2 * te + 1, cb = tc * 8;

    for (int tile = blockIdx.x; tile < N_EDGES / 64; tile += gridDim.x) {
        const int eg = tile * 64;
        __syncthreads();
        for (int i = t; i < 512; i += 256) sEF[i] = ef[(size_t)eg * 8 + i];
        sEA[t] = ea[(size_t)eg * 4 + t];
        if (t < 64)       sSrc[t] = src[eg + t];
        else if (t < 128) sDst[t - 64] = dst[eg + t - 64];
        __syncthreads();
        gemm_tile<8,  true>(sEF, 8,    sWr1, sHa, C_R1, e0l, e1l, cb);
        __syncthreads();
        gemm_tile<64, true>(sHa, ST_H, sWr2, sHb, C_R,  e0l, e1l, cb);
        __syncthreads();
        gemm_tile<64, true>(sHb, ST_H, sWr3, sHa, C_R,  e0l, e1l, cb);
        __syncthreads();

        // ---- fused layer-4 + messages ----
        const int sn[2] = {sSrc[e0l], sSrc[e1l]};
        const int dn[2] = {sDst[e0l], sDst[e1l]};
        const float* xr0 = g_x + (size_t)sn[0] * 256;
        const float* xr1 = g_x + (size_t)sn[1] * 256;
        float* mr0 = g_m + (size_t)dn[0] * 512;
        float* mr1 = g_m + (size_t)dn[1] * 512;
        float sh0[2] = {sEA[e0l*4+0], sEA[e1l*4+0]};
        float a1v[2] = {sEA[e0l*4+1], sEA[e1l*4+1]};
        float a2v[2] = {sEA[e0l*4+2], sEA[e1l*4+2]};
        float a3v[2] = {sEA[e0l*4+3], sEA[e1l*4+3]};

        float s[2][8];
        {
            float4 p = *(const float4*)(xr0 + cb);
            float4 q = *(const float4*)(xr0 + cb + 4);
            s[0][0]=p.x; s[0][1]=p.y; s[0][2]=p.z; s[0][3]=p.w;
            s[0][4]=q.x; s[0][5]=q.y; s[0][6]=q.z; s[0][7]=q.w;
            p = *(const float4*)(xr1 + cb);
            q = *(const float4*)(xr1 + cb + 4);
            s[1][0]=p.x; s[1][1]=p.y; s[1][2]=p.z; s[1][3]=p.w;
            s[1][4]=q.x; s[1][5]=q.y; s[1][6]=q.z; s[1][7]=q.w;
        }

        float acc[2][8];
        // cc=0: p0 -> m0[0:64]
        l4_acc(sHa, Wr4, e0l, e1l, cb, 0, acc);
        #pragma unroll
        for (int e = 0; e < 2; e++) {
            float* mr = e ? mr1 : mr0;
            red_add_v4(mr + cb,
                       acc[e][0]*s[e][0]*sh0[e], acc[e][1]*s[e][1]*sh0[e],
                       acc[e][2]*s[e][2]*sh0[e], acc[e][3]*s[e][3]*sh0[e]);
            red_add_v4(mr + cb + 4,
                       acc[e][4]*s[e][4]*sh0[e], acc[e][5]*s[e][5]*sh0[e],
                       acc[e][6]*s[e][6]*sh0[e], acc[e][7]*s[e][7]*sh0[e]);
        }
        // cc=1: p1 -> mrow[128 + u*3 + i]
        l4_acc(sHa, Wr4, e0l, e1l, cb, 1, acc);
        #pragma unroll
        for (int e = 0; e < 2; e++) {
            float* mr = e ? mr1 : mr0;
            float p[24];
            #pragma unroll
            for (int j = 0; j < 8; j++) {
                float ts = acc[e][j] * s[e][j];
                p[j*3+0] = ts * a1v[e];
                p[j*3+1] = ts * a2v[e];
                p[j*3+2] = ts * a3v[e];
            }
            float* b = mr + 128 + cb * 3;
            #pragma unroll
            for (int r = 0; r < 6; r++)
                red_add_v4(b + r*4, p[r*4], p[r*4+1], p[r*4+2], p[r*4+3]);
        }
        // gather v (x1) chunks
        float vv[2][24];
        #pragma unroll
        for (int i = 0; i < 6; i++) {
            float4 p = *(const float4*)(xr0 + 64 + cb*3 + i*4);
            vv[0][i*4+0]=p.x; vv[0][i*4+1]=p.y; vv[0][i*4+2]=p.z; vv[0][i*4+3]=p.w;
            float4 q = *(const float4*)(xr1 + 64 + cb*3 + i*4);
            vv[1][i*4+0]=q.x; vv[1][i*4+1]=q.y; vv[1][i*4+2]=q.z; vv[1][i*4+3]=q.w;
        }
        // cc=2: p2 -> mrow[320 + u*3 + i]
        l4_acc(sHa, Wr4, e0l, e1l, cb, 2, acc);
        #pragma unroll
        for (int e = 0; e < 2; e++) {
            float* mr = e ? mr1 : mr0;
            float p[24];
            #pragma unroll
            for (int j = 0; j < 8; j++) {
                float tv = acc[e][j] * sh0[e];
                p[j*3+0] = tv * vv[e][j*3+0];
                p[j*3+1] = tv * vv[e][j*3+1];
                p[j*3+2] = tv * vv[e][j*3+2];
            }
            float* b = mr + 320 + cb * 3;
            #pragma unroll
            for (int r = 0; r < 6; r++)
                red_add_v4(b + r*4, p[r*4], p[r*4+1], p[r*4+2], p[r*4+3]);
        }
        // cc=3: p3 -> m0[64:128]
        l4_acc(sHa, Wr4, e0l, e1l, cb, 3, acc);
        #pragma unroll
        for (int e = 0; e < 2; e++) {
            float* mr = e ? mr1 : mr0;
            float p[8];
            #pragma unroll
            for (int j = 0; j < 8; j++) {
                float dv = vv[e][j*3+0]*a1v[e] + vv[e][j*3+1]*a2v[e] + vv[e][j*3+2]*a3v[e];
                p[j] = acc[e][j] * dv * INV_SQRT3;
            }
            red_add_v4(mr + 64 + cb,     p[0], p[1], p[2], p[3]);
            red_add_v4(mr + 64 + cb + 4, p[4], p[5], p[6], p[7]);
        }
    }
}

// ==== K2: node output, 16 nodes/block, broadcast W_skip layout, 2 blocks/SM ====
#define NOB 16
#define O2_WL0 0
#define O2_WL1 8192
#define O2_Y   16384
#define K2_SMEM_FLOATS (O2_Y + NOB*256)   // 20480 floats -> 81920 B

__global__ __launch_bounds__(256, 2) void k_node_out(const float* __restrict__ na,
                                                     const float* __restrict__ Wl0,
                                                     const float* __restrict__ Wl1,
                                                     float* __restrict__ out) {
    extern __shared__ float sm[];
    float* sWl0 = sm + O2_WL0;
    float* sWl1 = sm + O2_WL1;
    float* sWt  = sm;                 // phase-B reuse of weight area (needs 10240)
    float* sY   = sm + O2_Y;
    const int t = threadIdx.x;
    const int n0 = blockIdx.x * NOB;
    for (int i = t; i < 8192; i += 256) { sWl0[i] = Wl0[i]; sWl1[i] = Wl1[i]; }
    __syncthreads();
    const int n4 = t >> 6, u = t & 63;

    // ---- phase A: y = m @ W_lin (m read via warp-broadcast ldg) ----
    float y[16];
    #pragma unroll
    for (int i = 0; i < 16; i++) y[i] = 0.f;
    #pragma unroll 4
    for (int v = 0; v < 128; v++) {
        float w0 = sWl0[v * 64 + u], w1 = sWl1[v * 64 + u];
        #pragma unroll
        for (int ns = 0; ns < 4; ns++) {
            const float* m = g_m + (size_t)(n0 + ns * 4 + n4) * 512;
            y[ns*4+0] += __ldg(m + v) * w0;
            y[ns*4+1] += __ldg(m + 128 + v*3 + 0) * w1;
            y[ns*4+2] += __ldg(m + 128 + v*3 + 1) * w1;
            y[ns*4+3] += __ldg(m + 128 + v*3 + 2) * w1;
        }
    }
    __syncthreads();   // phase A done reading sWl before overwrite below
    #pragma unroll
    for (int ns = 0; ns < 4; ns++) {
        float* yb = sY + (ns * 4 + n4) * 256;
        yb[u]       = y[ns*4+0] * C_LIN;
        yb[64 + u]  = y[ns*4+1] * C_LIN;
        yb[128 + u] = y[ns*4+2] * C_LIN;
        yb[192 + u] = y[ns*4+3] * C_LIN;
    }
    float areg[40];
    #pragma unroll
    for (int ns = 0; ns < 4; ns++)
        #pragma unroll
        for (int w = 0; w < 10; w++)
            areg[ns*10 + w] = __ldg(na + (size_t)(n0 + ns*4 + n4) * 10 + w);

    // ---- phase B: z = y . (a . W_skip), W_skip [v][w][u] streamed via smem ----
    float z[16];
    #pragma unroll
    for (int i = 0; i < 16; i++) z[i] = 0.f;
    for (int vc = 0; vc < 8; vc++) {
        __syncthreads();
        const int v0 = vc * 8;
        const float4* g0p = (const float4*)(g_wt0 + (size_t)v0 * 640);
        const float4* g1p = (const float4*)(g_wt1 + (size_t)v0 * 640);
        float4* d0 = (float4*)sWt;
        float4* d1 = (float4*)(sWt + 5120);
        for (int i = t; i < 1280; i += 256) { d0[i] = g0p[i]; d1[i] = g1p[i]; }
        __syncthreads();
        #pragma unroll
        for (int v = 0; v < 8; v++) {
            const float* w0b = sWt + v * 640 + u;
            const float* w1b = sWt + 5120 + v * 640 + u;
            float g0[4] = {0.f, 0.f, 0.f, 0.f}, g1[4] = {0.f, 0.f, 0.f, 0.f};
            #pragma unroll
            for (int w = 0; w < 10; w++) {
                float lw0 = w0b[w * 64];
                float lw1 = w1b[w * 64];
                #pragma unroll
                for (int ns = 0; ns < 4; ns++) {
                    g0[ns] += areg[ns*10 + w] * lw0;
                    g1[ns] += areg[ns*10 + w] * lw1;
                }
            }
            #pragma unroll
            for (int ns = 0; ns < 4; ns++) {
                const float* yp = sY + (ns * 4 + n4) * 256 + v0 + v;
                z[ns*4+0] += yp[0]   * g0[ns];
                z[ns*4+1] += yp[64]  * g1[ns];
                z[ns*4+2] += yp[128] * g1[ns];
                z[ns*4+3] += yp[192] * g1[ns];
            }
        }
    }
    #pragma unroll
    for (int ns = 0; ns < 4; ns++) {
        float* o = out + (size_t)(n0 + ns * 4 + n4) * 256;
        o[u]            = z[ns*4+0] * C_SKIP;
        o[64 + u*3 + 0] = z[ns*4+1] * C_SKIP;
        o[64 + u*3 + 1] = z[ns*4+2] * C_SKIP;
        o[64 + u*3 + 2] = z[ns*4+3] * C_SKIP;
    }
}

extern "C" void kernel_launch(void* const* d_in, const int* in_sizes, int n_in,
                              void* d_out, int out_size) {
    const float* nf  = (const float*)d_in[0];
    const float* na  = (const float*)d_in[1];
    const float* ef  = (const float*)d_in[2];
    const float* ea  = (const float*)d_in[3];
    const int*   src = (const int*)d_in[4];
    const int*   dst = (const int*)d_in[5];
    const float* Wu0 = (const float*)d_in[6];
    const float* Wu1 = (const float*)d_in[7];
    const float* Wr1 = (const float*)d_in[8];
    const float* Wr2 = (const float*)d_in[9];
    const float* Wr3 = (const float*)d_in[10];
    const float* Wr4 = (const float*)d_in[11];
    const float* Wl0 = (const float*)d_in[12];
    const float* Wl1 = (const float*)d_in[13];
    const float* Ws0 = (const float*)d_in[14];
    const float* Ws1 = (const float*)d_in[15];
    float* out = (float*)d_out;

    cudaFuncSetAttribute(k_edge, cudaFuncAttributeMaxDynamicSharedMemorySize,
                         K1_SMEM_FLOATS * 4);
    cudaFuncSetAttribute(k_node_out, cudaFuncAttributeMaxDynamicSharedMemorySize,
                         K2_SMEM_FLOATS * 4);

    void* gm_ptr = nullptr;
    cudaGetSymbolAddress(&gm_ptr, g_m);
    cudaMemsetAsync(gm_ptr, 0, sizeof(float) * (size_t)N_NODES * 512, 0);

    k_prep<<<160, 256>>>(Ws0, Ws1);
    k_node_up<<<N_NODES / 8, 256>>>(nf, Wu0, Wu1);
    k_edge<<<296, 256, K1_SMEM_FLOATS * 4>>>(ef, ea, src, dst, Wr1, Wr2, Wr3, Wr4);
    k_node_out<<<N_NODES / NOB, 256, K2_SMEM_FLOATS * 4>>>(na, Wl0, Wl1, out);
}

// round 11
// speedup vs baseline: 1.4371x; 1.0477x over previous
#include <cuda_runtime.h>
#include <cuda_fp16.h>
#include <cstdint>
#include <cstddef>

#define N_NODES 32768
#define N_EDGES 524288

// ---- scratch (device globals; allocations forbidden) ----
__device__ float  g_x[(size_t)N_NODES * 256];     // [0:64]=x0, [64+u*3+i]=x1[u][i]
__device__ float  g_m[(size_t)N_NODES * 512];     // [0:128]=m0, [128+v*3+i]=m1
__device__ __half g_tpw[(size_t)N_EDGES * 256];   // per-edge radial MLP output (fp16)
__device__ float  g_wt0[64 * 64 * 12];            // W_skip0 as [v][u][w-pad12]
__device__ float  g_wt1[64 * 64 * 12];
__device__ int    g_cnt[N_NODES];                 // histogram
__device__ int    g_cur[N_NODES];                 // scatter cursor
__device__ int    g_rowptr[N_NODES + 1];
__device__ int    g_eid[N_EDGES];

#define C_UP      0.125f
#define C_R1      0.35355339059327373f
#define C_R       0.125f
#define C_LIN     0.00552427172801990f
#define C_SKIP    0.03952847075210474f
#define INV_SQRT3 0.5773502691896258f

__device__ __forceinline__ float silu_f(float x) {
    return __fdividef(x, 1.0f + __expf(-x));
}
__device__ __forceinline__ unsigned int h2_bits(__half2 h) {
    return *reinterpret_cast<unsigned int*>(&h);
}

// ==== K_prep: W_skip (64,64,10)[u,v,w] -> [v][u][12] (w-padded) ====
__global__ void k_prep(const float* __restrict__ Ws0, const float* __restrict__ Ws1) {
    int idx = blockIdx.x * 256 + threadIdx.x;   // 0 .. 49151
    int v = idx / 768;
    int r = idx % 768;
    int u = r / 12, w = r % 12;
    float a = 0.f, b = 0.f;
    if (w < 10) {
        a = Ws0[u * 640 + v * 10 + w];
        b = Ws1[u * 640 + v * 10 + w];
    }
    g_wt0[idx] = a;
    g_wt1[idx] = b;
}

// ==== K0: node up-projection (8 nodes/block) ====
__global__ __launch_bounds__(256) void k_node_up(const float* __restrict__ nf,
                                                 const float* __restrict__ Wu0,
                                                 const float* __restrict__ Wu1) {
    __shared__ float sW0[4096], sW1[4096], sIn[2048];
    const int t = threadIdx.x;
    for (int i = t; i < 4096; i += 256) { sW0[i] = Wu0[i]; sW1[i] = Wu1[i]; }
    const int n0 = blockIdx.x * 8;
    for (int i = t; i < 2048; i += 256) sIn[i] = nf[(size_t)n0 * 256 + i];
    __syncthreads();
    const int j = t >> 6, u = t & 63;
    const int off0 = (j == 0) ? 0 : (63 + j);
    const int st = (j == 0) ? 1 : 3;
    const float* W = (j == 0) ? sW0 : sW1;
    const int oo = (j == 0) ? u : (64 + u * 3 + (j - 1));
    for (int c = 0; c < 2; c++) {
        float acc[4] = {0.f, 0.f, 0.f, 0.f};
        #pragma unroll 8
        for (int v = 0; v < 64; v++) {
            float w = W[v * 64 + u];
            #pragma unroll
            for (int r = 0; r < 4; r++)
                acc[r] += sIn[(c * 4 + r) * 256 + off0 + v * st] * w;
        }
        #pragma unroll
        for (int r = 0; r < 4; r++)
            g_x[(size_t)(n0 + c * 4 + r) * 256 + oo] = acc[r] * C_UP;
    }
}

// ==== CSR build over dst ====
__global__ void k_hist(const int* __restrict__ dst) {
    int e = blockIdx.x * 256 + threadIdx.x;
    atomicAdd(&g_cnt[dst[e]], 1);
}

__global__ __launch_bounds__(1024) void k_scan() {
    __shared__ int part[1024];
    const int t = threadIdx.x;
    int loc[32];
    int s = 0;
    #pragma unroll
    for (int j = 0; j < 32; j++) { loc[j] = s; s += g_cnt[t * 32 + j]; }
    part[t] = s;
    __syncthreads();
    for (int off = 1; off < 1024; off <<= 1) {
        int v = (t >= off) ? part[t - off] : 0;
        __syncthreads();
        part[t] += v;
        __syncthreads();
    }
    int pre = (t == 0) ? 0 : part[t - 1];
    #pragma unroll
    for (int j = 0; j < 32; j++) {
        int o = pre + loc[j];
        g_rowptr[t * 32 + j] = o;
        g_cur[t * 32 + j] = o;
    }
    if (t == 1023) g_rowptr[N_NODES] = part[1023];
}

__global__ void k_scatter(const int* __restrict__ dst) {
    int e = blockIdx.x * 256 + threadIdx.x;
    int p = atomicAdd(&g_cur[dst[e]], 1);
    g_eid[p] = e;
}

// ==== K1: radial MLP only -> g_tpw (fp16). 512 threads, 128 edges/tile ====
#define ST_H 65
#define OFF_WR1 0
#define OFF_WR2 512
#define OFF_WR3 4608
#define OFF_WR4 8704
#define OFF_HA  25088
#define OFF_HB  (OFF_HA + 128*ST_H)       // 33408
#define OFF_EF  (OFF_HB + 128*ST_H)       // 41728
#define K1_SMEM_FLOATS (OFF_EF + 1024)    // 42752 floats -> 171008 B

template<int K, bool SILU>
__device__ __forceinline__ void gemm_t(const float* __restrict__ A, int astride,
                                       const float* __restrict__ B,
                                       float* __restrict__ O,
                                       float scale, int e0, int e1, int cb) {
    float acc[2][8];
    #pragma unroll
    for (int r = 0; r < 2; r++)
        #pragma unroll
        for (int j = 0; j < 8; j++) acc[r][j] = 0.f;
    #pragma unroll 8
    for (int k = 0; k < K; k++) {
        float a0 = A[e0 * astride + k];
        float a1 = A[e1 * astride + k];
        const float4 b0 = *(const float4*)(B + k * 64 + cb);
        const float4 b1 = *(const float4*)(B + k * 64 + cb + 4);
        acc[0][0] += a0*b0.x; acc[0][1] += a0*b0.y; acc[0][2] += a0*b0.z; acc[0][3] += a0*b0.w;
        acc[0][4] += a0*b1.x; acc[0][5] += a0*b1.y; acc[0][6] += a0*b1.z; acc[0][7] += a0*b1.w;
        acc[1][0] += a1*b0.x; acc[1][1] += a1*b0.y; acc[1][2] += a1*b0.z; acc[1][3] += a1*b0.w;
        acc[1][4] += a1*b1.x; acc[1][5] += a1*b1.y; acc[1][6] += a1*b1.z; acc[1][7] += a1*b1.w;
    }
    #pragma unroll
    for (int r = 0; r < 2; r++) {
        const int e = r ? e1 : e0;
        #pragma unroll
        for (int j = 0; j < 8; j++) {
            float x = acc[r][j] * scale;
            O[e * ST_H + cb + j] = SILU ? silu_f(x) : x;
        }
    }
}

__device__ __forceinline__ void l4_store(const float* __restrict__ H,
                                         const float* __restrict__ W4,
                                         __half* __restrict__ gout,
                                         int e0, int e1, int cb) {
    #pragma unroll
    for (int cc = 0; cc < 4; cc++) {
        float acc[2][8];
        #pragma unroll
        for (int r = 0; r < 2; r++)
            #pragma unroll
            for (int j = 0; j < 8; j++) acc[r][j] = 0.f;
        const float* B = W4 + cc * 64 + cb;
        #pragma unroll 8
        for (int k = 0; k < 64; k++) {
            float a0 = H[e0 * ST_H + k];
            float a1 = H[e1 * ST_H + k];
            const float4 b0 = *(const float4*)(B + k * 256);
            const float4 b1 = *(const float4*)(B + k * 256 + 4);
            acc[0][0] += a0*b0.x; acc[0][1] += a0*b0.y; acc[0][2] += a0*b0.z; acc[0][3] += a0*b0.w;
            acc[0][4] += a0*b1.x; acc[0][5] += a0*b1.y; acc[0][6] += a0*b1.z; acc[0][7] += a0*b1.w;
            acc[1][0] += a1*b0.x; acc[1][1] += a1*b0.y; acc[1][2] += a1*b0.z; acc[1][3] += a1*b0.w;
            acc[1][4] += a1*b1.x; acc[1][5] += a1*b1.y; acc[1][6] += a1*b1.z; acc[1][7] += a1*b1.w;
        }
        #pragma unroll
        for (int r = 0; r < 2; r++) {
            const int e = r ? e1 : e0;
            __half2 h0 = __floats2half2_rn(acc[r][0]*C_R, acc[r][1]*C_R);
            __half2 h1 = __floats2half2_rn(acc[r][2]*C_R, acc[r][3]*C_R);
            __half2 h2 = __floats2half2_rn(acc[r][4]*C_R, acc[r][5]*C_R);
            __half2 h3 = __floats2half2_rn(acc[r][6]*C_R, acc[r][7]*C_R);
            uint4 pk;
            pk.x = h2_bits(h0); pk.y = h2_bits(h1);
            pk.z = h2_bits(h2); pk.w = h2_bits(h3);
            *(uint4*)(gout + (size_t)e * 256 + cc * 64 + cb) = pk;
        }
    }
}

__global__ __launch_bounds__(512, 1) void k_edge_mlp(const float* __restrict__ ef,
                                                     const float* __restrict__ Wr1,
                                                     const float* __restrict__ Wr2,
                                                     const float* __restrict__ Wr3,
                                                     const float* __restrict__ Wr4) {
    extern __shared__ float sm[];
    float* sWr1 = sm + OFF_WR1;
    float* sWr2 = sm + OFF_WR2;
    float* sWr3 = sm + OFF_WR3;
    float* sWr4 = sm + OFF_WR4;
    float* sHa  = sm + OFF_HA;
    float* sHb  = sm + OFF_HB;
    float* sEF  = sm + OFF_EF;
    const int t = threadIdx.x;
    if (t < 512) sWr1[t] = Wr1[t];
    for (int i = t; i < 4096;  i += 512) { sWr2[i] = Wr2[i]; sWr3[i] = Wr3[i]; }
    for (int i = t; i < 16384; i += 512) sWr4[i] = Wr4[i];
    const int te = t >> 3, tc = t & 7;
    const int e0 = te * 2, e1 = te * 2 + 1, cb = tc * 8;

    for (int tile = blockIdx.x; tile < N_EDGES / 128; tile += gridDim.x) {
        const int eg = tile * 128;
        __syncthreads();
        for (int i = t; i < 1024; i += 512) sEF[i] = ef[(size_t)eg * 8 + i];
        __syncthreads();
        gemm_t<8,  true>(sEF, 8,    sWr1, sHa, C_R1, e0, e1, cb);
        __syncthreads();
        gemm_t<64, true>(sHa, ST_H, sWr2, sHb, C_R,  e0, e1, cb);
        __syncthreads();
        gemm_t<64, true>(sHb, ST_H, sWr3, sHa, C_R,  e0, e1, cb);
        __syncthreads();
        l4_store(sHa, sWr4, g_tpw + (size_t)eg * 256, e0, e1, cb);
    }
}

// ==== K_gather: CSR walk per node, atomic-free accumulation ====
__global__ __launch_bounds__(256) void k_gather(const float* __restrict__ ea,
                                                const int* __restrict__ src) {
    const int t = threadIdx.x;
    const int n = blockIdx.x * 4 + (t >> 6);
    const int u = t & 63;
    const int beg = g_rowptr[n], end = g_rowptr[n + 1];
    float m0a = 0.f, m0b = 0.f;
    float m1a0 = 0.f, m1a1 = 0.f, m1a2 = 0.f;
    float m1b0 = 0.f, m1b1 = 0.f, m1b2 = 0.f;
    for (int idx = beg; idx < end; idx++) {
        const int e = g_eid[idx];
        const float sh0 = __ldg(ea + (size_t)e * 4 + 0);
        const float a1  = __ldg(ea + (size_t)e * 4 + 1);
        const float a2  = __ldg(ea + (size_t)e * 4 + 2);
        const float a3  = __ldg(ea + (size_t)e * 4 + 3);
        const int sn = __ldg(src + e);
        const float* xr = g_x + (size_t)sn * 256;
        const float s  = xr[u];
        const float v0 = xr[64 + u * 3 + 0];
        const float v1 = xr[64 + u * 3 + 1];
        const float v2 = xr[64 + u * 3 + 2];
        const __half* tp = g_tpw + (size_t)e * 256;
        const float t0 = __half2float(tp[u]);
        const float t1 = __half2float(tp[64 + u]);
        const float t2 = __half2float(tp[128 + u]);
        const float t3 = __half2float(tp[192 + u]);
        m0a += t0 * s * sh0;
        const float dv = v0 * a1 + v1 * a2 + v2 * a3;
        m0b += t3 * dv * INV_SQRT3;
        const float ts = t1 * s;
        m1a0 += ts * a1; m1a1 += ts * a2; m1a2 += ts * a3;
        const float tv = t2 * sh0;
        m1b0 += tv * v0; m1b1 += tv * v1; m1b2 += tv * v2;
    }
    float* mr = g_m + (size_t)n * 512;
    mr[u] = m0a;
    mr[64 + u] = m0b;
    mr[128 + u * 3 + 0] = m1a0;
    mr[128 + u * 3 + 1] = m1a1;
    mr[128 + u * 3 + 2] = m1a2;
    mr[320 + u * 3 + 0] = m1b0;
    mr[320 + u * 3 + 1] = m1b1;
    mr[320 + u * 3 + 2] = m1b2;
}

// ==== K2: node output, 16 nodes/block (R3 proven version) ====
#define NOB 16
#define O2_WL0 0
#define O2_WL1 8192
#define O2_M   16384
#define O2_Y   24576
#define O2_A   28672
#define K2_SMEM_FLOATS (O2_A + 192)

__global__ __launch_bounds__(256, 2) void k_node_out(const float* __restrict__ na,
                                                     const float* __restrict__ Wl0,
                                                     const float* __restrict__ Wl1,
                                                     float* __restrict__ out) {
    extern __shared__ float sm[];
    float* sWl0 = sm + O2_WL0;
    float* sWl1 = sm + O2_WL1;
    float* sWt  = sm;                 // phase-B reuse (12288 floats)
    float* sM   = sm + O2_M;
    float* sY   = sm + O2_Y;
    float* sA   = sm + O2_A;
    const int t = threadIdx.x;
    const int n0 = blockIdx.x * NOB;
    for (int i = t; i < 8192; i += 256) { sWl0[i] = Wl0[i]; sWl1[i] = Wl1[i]; }
    for (int i = t; i < NOB * 512; i += 256) sM[i] = g_m[(size_t)n0 * 512 + i];
    for (int i = t; i < NOB * 12; i += 256) {
        int n = i / 12, w = i % 12;
        sA[i] = (w < 10) ? na[(size_t)(n0 + n) * 10 + w] : 0.f;
    }
    __syncthreads();
    const int n4 = t >> 6, u = t & 63;

    // ---- phase A: y = m @ W_lin ----
    float y[16];
    #pragma unroll
    for (int i = 0; i < 16; i++) y[i] = 0.f;
    #pragma unroll 4
    for (int v = 0; v < 128; v++) {
        float w0 = sWl0[v * 64 + u], w1 = sWl1[v * 64 + u];
        #pragma unroll
        for (int ns = 0; ns < 4; ns++) {
            const float* m = sM + (ns * 4 + n4) * 512;
            y[ns*4+0] += m[v] * w0;
            y[ns*4+1] += m[128 + v*3 + 0] * w1;
            y[ns*4+2] += m[128 + v*3 + 1] * w1;
            y[ns*4+3] += m[128 + v*3 + 2] * w1;
        }
    }
    #pragma unroll
    for (int ns = 0; ns < 4; ns++) {
        float* yb = sY + (ns * 4 + n4) * 256;
        yb[u]       = y[ns*4+0] * C_LIN;
        yb[64 + u]  = y[ns*4+1] * C_LIN;
        yb[128 + u] = y[ns*4+2] * C_LIN;
        yb[192 + u] = y[ns*4+3] * C_LIN;
    }
    float areg[40];
    #pragma unroll
    for (int ns = 0; ns < 4; ns++)
        #pragma unroll
        for (int w = 0; w < 10; w++)
            areg[ns*10 + w] = sA[(ns*4 + n4) * 12 + w];

    // ---- phase B: z = y . (a . W_skip), W_skip streamed via smem ----
    float z[16];
    #pragma unroll
    for (int i = 0; i < 16; i++) z[i] = 0.f;
    for (int vc = 0; vc < 8; vc++) {
        __syncthreads();
        const int v0 = vc * 8;
        const float4* g0p = (const float4*)(g_wt0 + (size_t)v0 * 768);
        const float4* g1p = (const float4*)(g_wt1 + (size_t)v0 * 768);
        float4* d0 = (float4*)sWt;
        float4* d1 = (float4*)(sWt + 6144);
        for (int i = t; i < 1536; i += 256) { d0[i] = g0p[i]; d1[i] = g1p[i]; }
        __syncthreads();
        #pragma unroll
        for (int v = 0; v < 8; v++) {
            const float* w0p = sWt + (v * 64 + u) * 12;
            const float* w1p = sWt + 6144 + (v * 64 + u) * 12;
            float4 wa0 = *(const float4*)(w0p);
            float4 wa1 = *(const float4*)(w0p + 4);
            float4 wa2 = *(const float4*)(w0p + 8);
            float4 wb0 = *(const float4*)(w1p);
            float4 wb1 = *(const float4*)(w1p + 4);
            float4 wb2 = *(const float4*)(w1p + 8);
            #pragma unroll
            for (int ns = 0; ns < 4; ns++) {
                const float* a = areg + ns * 10;
                float g0 = a[0]*wa0.x + a[1]*wa0.y + a[2]*wa0.z + a[3]*wa0.w
                         + a[4]*wa1.x + a[5]*wa1.y + a[6]*wa1.z + a[7]*wa1.w
                         + a[8]*wa2.x + a[9]*wa2.y;
                float g1 = a[0]*wb0.x + a[1]*wb0.y + a[2]*wb0.z + a[3]*wb0.w
                         + a[4]*wb1.x + a[5]*wb1.y + a[6]*wb1.z + a[7]*wb1.w
                         + a[8]*wb2.x + a[9]*wb2.y;
                const float* yp = sY + (ns * 4 + n4) * 256 + v0 + v;
                z[ns*4+0] += yp[0]   * g0;
                z[ns*4+1] += yp[64]  * g1;
                z[ns*4+2] += yp[128] * g1;
                z[ns*4+3] += yp[192] * g1;
            }
        }
    }
    #pragma unroll
    for (int ns = 0; ns < 4; ns++) {
        float* o = out + (size_t)(n0 + ns * 4 + n4) * 256;
        o[u]            = z[ns*4+0] * C_SKIP;
        o[64 + u*3 + 0] = z[ns*4+1] * C_SKIP;
        o[64 + u*3 + 1] = z[ns*4+2] * C_SKIP;
        o[64 + u*3 + 2] = z[ns*4+3] * C_SKIP;
    }
}

extern "C" void kernel_launch(void* const* d_in, const int* in_sizes, int n_in,
                              void* d_out, int out_size) {
    const float* nf  = (const float*)d_in[0];
    const float* na  = (const float*)d_in[1];
    const float* ef  = (const float*)d_in[2];
    const float* ea  = (const float*)d_in[3];
    const int*   src = (const int*)d_in[4];
    const int*   dst = (const int*)d_in[5];
    const float* Wu0 = (const float*)d_in[6];
    const float* Wu1 = (const float*)d_in[7];
    const float* Wr1 = (const float*)d_in[8];
    const float* Wr2 = (const float*)d_in[9];
    const float* Wr3 = (const float*)d_in[10];
    const float* Wr4 = (const float*)d_in[11];
    const float* Wl0 = (const float*)d_in[12];
    const float* Wl1 = (const float*)d_in[13];
    const float* Ws0 = (const float*)d_in[14];
    const float* Ws1 = (const float*)d_in[15];
    float* out = (float*)d_out;

    cudaFuncSetAttribute(k_edge_mlp, cudaFuncAttributeMaxDynamicSharedMemorySize,
                         K1_SMEM_FLOATS * 4);
    cudaFuncSetAttribute(k_node_out, cudaFuncAttributeMaxDynamicSharedMemorySize,
                         K2_SMEM_FLOATS * 4);

    void* cnt_ptr = nullptr;
    cudaGetSymbolAddress(&cnt_ptr, g_cnt);
    cudaMemsetAsync(cnt_ptr, 0, sizeof(int) * N_NODES, 0);

    k_prep<<<192, 256>>>(Ws0, Ws1);
    k_node_up<<<N_NODES / 8, 256>>>(nf, Wu0, Wu1);
    k_hist<<<N_EDGES / 256, 256>>>(dst);
    k_scan<<<1, 1024>>>();
    k_scatter<<<N_EDGES / 256, 256>>>(dst);
    k_edge_mlp<<<148, 512, K1_SMEM_FLOATS * 4>>>(ef, Wr1, Wr2, Wr3, Wr4);
    k_gather<<<N_NODES / 4, 256>>>(ea, src);
    k_node_out<<<N_NODES / NOB, 256, K2_SMEM_FLOATS * 4>>>(na, Wl0, Wl1, out);
}